// round 2
// baseline (speedup 1.0000x reference)
#include <cuda_runtime.h>

// MMSolver: 128x128 LLG micromagnetics, 356 RK4 steps (100 relax + 256 driven).
// Persistent kernel, 128 CTAs (one 8x16 tile each), software global barrier.
// Each "superstep" fuses 2 RK4 steps (8 torque stages) using a halo-8 region
// (24x32) held in shared memory; only __syncthreads between stages.
// Global m state lives in a __device__ array, accessed with .cg (L2) ops so
// cross-SM coherence is guaranteed by threadfence + the barrier.

#define NXY 128
#define TI 8            // tile rows (i)
#define TJ 16           // tile cols (j)
#define HALO 8          // 2 RK4 steps * 4 stages
#define RI (TI + 2*HALO)   // 24
#define RJ (TJ + 2*HALO)   // 32
#define RJP 33             // padded row
#define NCTA 128
#define NTHREADS (RI*RJ)   // 768
#define RELAX_STEPS_C 100
#define T_SIG 256
#define NSTEPS (RELAX_STEPS_C + T_SIG)   // 356
#define SPS 2
#define NSS (NSTEPS/SPS)   // 178

#define HH        0.017595f          // GAMMA*DT
#define C_SOT_F   0.001f
#define MU0_F     1.2566370614359173e-06f
#define CEX_NUM   (2.0f*1.3e-11f/(5e-9f*5e-9f))   // 2*A_EX/DX^2 = 1.04e6

__device__ float g_m[3][NXY][NXY];
__device__ unsigned int g_bar_count;
__device__ unsigned int g_bar_gen;

__global__ void __launch_bounds__(NTHREADS, 1)
mm_kernel(const float* __restrict__ signal,
          const float* __restrict__ B_ext,
          const float* __restrict__ Msat,
          const int*   __restrict__ src_idx,
          const int*   __restrict__ probe_idx,
          float*       __restrict__ out)
{
    __shared__ float sm[2][3][RI][RJP];
    __shared__ unsigned int s_gen;

    const int tid = threadIdx.x;
    if (tid == 0) s_gen = *(volatile unsigned int*)&g_bar_gen;

    const int ri = tid >> 5;        // 0..23
    const int rj = tid & 31;        // 0..31
    const int bi = blockIdx.x >> 3; // 0..15
    const int bj = blockIdx.x & 7;  // 0..7
    const int gi = bi * TI - HALO + ri;
    const int gj = bj * TJ - HALO + rj;
    const bool in_dom = (gi >= 0 && gi < NXY && gj >= 0 && gj < NXY);
    const int gci = min(max(gi, 0), NXY - 1);
    const int gcj = min(max(gj, 0), NXY - 1);
    // neighbor region indices, clamped at the DOMAIN boundary (edge-replicate BC)
    const int riN = (gi <= 0)       ? ri : ri - 1;
    const int riS = (gi >= NXY - 1) ? ri : ri + 1;
    const int rjW = (gj <= 0)       ? rj : rj - 1;
    const int rjE = (gj >= NXY - 1) ? rj : rj + 1;

    // per-cell statics
    float Bx = 0.f, By = 0.f, Bzs = 0.f, cex = 0.f, dem = 0.f, msat = 0.f;
    if (in_dom) {
        int g = gi * NXY + gj;
        Bx   = B_ext[0 * NXY * NXY + g];
        By   = B_ext[1 * NXY * NXY + g];
        Bzs  = B_ext[2 * NXY * NXY + g];
        msat = Msat[g];
        cex  = CEX_NUM / msat;
        dem  = -MU0_F * msat;
    }
    // src slot: last match wins (matches JAX .set scatter with duplicate idx)
    int srcslot = -1;
    #pragma unroll
    for (int s = 0; s < 2; s++)
        if (src_idx[2 * s] == gi && src_idx[2 * s + 1] == gj) srcslot = s;

    const bool is_tile = (ri >= HALO && ri < HALO + TI && rj >= HALO && rj < HALO + TJ);
    int probemask = 0;
    if (is_tile && in_dom) {
        #pragma unroll
        for (int p = 0; p < 4; p++)
            if (probe_idx[2 * p] == gi && probe_idx[2 * p + 1] == gj) probemask |= 1 << p;
    }
    float probe_base = 0.f;

    __syncthreads();
    unsigned int gen = s_gen;

    float m0x, m0y, m0z;   // m at step start
    float cmx, cmy, cmz;   // current stage value of own cell
    int cur = 0;

    const float* gm = &g_m[0][0][0];

    for (int ss = 0; ss < NSS; ++ss) {
        // ---- load region ----
        if (ss == 0) {
            cmx = 0.f; cmy = 1.f; cmz = 0.f;   // m_init = y-hat
        } else {
            int g = gci * NXY + gcj;
            cmx = __ldcg(gm + g);
            cmy = __ldcg(gm + NXY * NXY + g);
            cmz = __ldcg(gm + 2 * NXY * NXY + g);
        }
        sm[cur][0][ri][rj] = cmx;
        sm[cur][1][ri][rj] = cmy;
        sm[cur][2][ri][rj] = cmz;
        m0x = cmx; m0y = cmy; m0z = cmz;
        __syncthreads();

        #pragma unroll
        for (int s = 0; s < SPS; ++s) {
            const int step = ss * SPS + s;
            const bool relax = (step < RELAX_STEPS_C);
            const float alpha = relax ? 0.5f : 0.02f;
            const float coef  = 1.0f / (1.0f + alpha * alpha);
            float bz = Bzs;
            if (!relax && srcslot >= 0)
                bz = __ldg(&signal[(step - RELAX_STEPS_C) * 2 + srcslot]);

            float ax = 0.f, ay = 0.f, az = 0.f;   // k1 + 2k2 + 2k3

            #pragma unroll
            for (int st = 0; st < 4; ++st) {
                const int q = s * 4 + st;          // shrink index 0..7
                const bool comp = in_dom && ri > q && ri < RI - 1 - q
                                         && rj > q && rj < RJ - 1 - q;
                float kx = 0.f, ky = 0.f, kz = 0.f;
                if (comp) {
                    float lx = sm[cur][0][riN][rj] + sm[cur][0][riS][rj]
                             + sm[cur][0][ri][rjW] + sm[cur][0][ri][rjE] - 4.f * cmx;
                    float ly = sm[cur][1][riN][rj] + sm[cur][1][riS][rj]
                             + sm[cur][1][ri][rjW] + sm[cur][1][ri][rjE] - 4.f * cmy;
                    float lz = sm[cur][2][riN][rj] + sm[cur][2][riS][rj]
                             + sm[cur][2][ri][rjW] + sm[cur][2][ri][rjE] - 4.f * cmz;
                    float bx  = Bx + cex * lx;
                    float by  = By + cex * ly;
                    float bzv = bz + cex * lz + dem * cmz;
                    // c = m x B
                    float cx = cmy * bzv - cmz * by;
                    float cy = cmz * bx  - cmx * bzv;
                    float cz = cmx * by  - cmy * bx;
                    // d = m x c
                    float dx = cmy * cz - cmz * cy;
                    float dy = cmz * cx - cmx * cz;
                    float dz = cmx * cy - cmy * cx;
                    // sot = C_SOT * m x (m x yhat)
                    float sx =  C_SOT_F * (cmx * cmy);
                    float sy = -C_SOT_F * (cmx * cmx + cmz * cmz);
                    float sz =  C_SOT_F * (cmy * cmz);
                    kx = sx - coef * (cx + alpha * dx);
                    ky = sy - coef * (cy + alpha * dy);
                    kz = sz - coef * (cz + alpha * dz);
                }
                const int nxt = cur ^ 1;
                if (comp) {
                    if (st < 3) {
                        const float w = (st == 0) ? 1.f : 2.f;
                        ax += w * kx; ay += w * ky; az += w * kz;
                        const float c = (st == 2) ? HH : (0.5f * HH);
                        cmx = m0x + c * kx;
                        cmy = m0y + c * ky;
                        cmz = m0z + c * kz;
                    } else {
                        cmx = m0x + (HH / 6.f) * (ax + kx);
                        cmy = m0y + (HH / 6.f) * (ay + ky);
                        cmz = m0z + (HH / 6.f) * (az + kz);
                        m0x = cmx; m0y = cmy; m0z = cmz;   // step complete
                    }
                    sm[nxt][0][ri][rj] = cmx;
                    sm[nxt][1][ri][rj] = cmy;
                    sm[nxt][2][ri][rj] = cmz;
                }
                cur = nxt;
                __syncthreads();
            }

            // probe readout (tile-interior cells are valid after every step)
            if (probemask) {
                if (step == RELAX_STEPS_C - 1) {
                    probe_base = m0z;
                } else if (step >= RELAX_STEPS_C) {
                    const float v = (m0z - probe_base) * msat;
                    const int t = step - RELAX_STEPS_C;
                    #pragma unroll
                    for (int p = 0; p < 4; p++)
                        if ((probemask >> p) & 1) out[t * 4 + p] = v;
                }
            }
        }

        // ---- write back owned tile ----
        if (is_tile) {
            int g = gi * NXY + gj;
            __stcg((float*)gm + g,                 m0x);
            __stcg((float*)gm + NXY * NXY + g,     m0y);
            __stcg((float*)gm + 2 * NXY * NXY + g, m0z);
        }

        // ---- global software barrier (all CTAs co-resident: 128 <= 148 SMs) ----
        if (ss < NSS - 1) {
            __syncthreads();
            if (tid == 0) {
                __threadfence();
                if (atomicAdd(&g_bar_count, 1u) == NCTA - 1) {
                    atomicExch(&g_bar_count, 0u);
                    __threadfence();
                    atomicExch(&g_bar_gen, gen + 1u);
                } else {
                    while (*(volatile unsigned int*)&g_bar_gen == gen) { }
                    __threadfence();
                }
            }
            gen++;
            __syncthreads();
        }
    }
}

extern "C" void kernel_launch(void* const* d_in, const int* in_sizes, int n_in,
                              void* d_out, int out_size)
{
    (void)in_sizes; (void)n_in; (void)out_size;
    mm_kernel<<<NCTA, NTHREADS>>>(
        (const float*)d_in[0],   // signal (1,256,2)
        (const float*)d_in[1],   // B_ext  (1,3,128,128)
        (const float*)d_in[2],   // Msat   (1,1,128,128)
        (const int*)d_in[3],     // src_idx (2,2)
        (const int*)d_in[4],     // probe_idx (4,2)
        (float*)d_out);          // (1,256,4)
}